// round 1
// baseline (speedup 1.0000x reference)
#include <cuda_runtime.h>
#include <cstdint>
#include <cstddef>

#define Bsz   64
#define Tlen  512
#define HID   1024
#define VOC   128
#define GRID  128
#define CPC   8          // hidden columns owned per CTA
#define NTHR  256

// ---------------- persistent device scratch (no allocations allowed) ----------
__device__ float g_hT[HID * Bsz];                       // h, transposed [k][b]
__device__ float g_rhT[HID * Bsz];                      // r*h, transposed [k][b]
__device__ float g_hist[(size_t)Tlen * HID * Bsz];      // [t][k][b]  (134 MB)
__device__ unsigned g_cnt = 0;
__device__ volatile unsigned g_gen = 0;

// ---------------- helpers -----------------------------------------------------
__device__ __forceinline__ void ffma2(unsigned long long &acc,
                                      unsigned long long a,
                                      unsigned long long b) {
    asm volatile("fma.rn.f32x2 %0, %1, %2, %0;" : "+l"(acc) : "l"(a), "l"(b));
}

__device__ __forceinline__ ulonglong2 ldg_cg_u2(const float* p) {
    ulonglong2 r;
    asm volatile("ld.global.cg.v2.u64 {%0, %1}, [%2];"
                 : "=l"(r.x), "=l"(r.y) : "l"(p));
    return r;
}

__device__ __forceinline__ void unpack2(unsigned long long v, float &lo, float &hi) {
    asm("mov.b64 {%0, %1}, %2;" : "=f"(lo), "=f"(hi) : "l"(v));
}

__device__ __forceinline__ float sigmoidf_(float x) {
    return 1.0f / (1.0f + __expf(-x));
}

// grid-wide sense-reversal barrier; the gpu-scope fences also flush L1D
// (CCTL.IVALL) so plain loads after the barrier see other CTAs' stores.
__device__ __forceinline__ void gbar() {
    __syncthreads();
    if (threadIdx.x == 0) {
        unsigned g = g_gen;
        __threadfence();
        unsigned a = atomicAdd(&g_cnt, 1u);
        if (a == GRID - 1) {
            g_cnt = 0;
            __threadfence();
            g_gen = g + 1;
        } else {
            while (g_gen == g) { }
            __threadfence();
        }
    }
    __syncthreads();
}

// ---------------- persistent GRU recurrence kernel -----------------------------
__global__ void __launch_bounds__(NTHR, 1)
gru_step_kernel(const int* __restrict__ X,
                const float* __restrict__ Wr_x, const float* __restrict__ b_r,
                const float* __restrict__ Wz_x, const float* __restrict__ b_z,
                const float* __restrict__ Wh_x, const float* __restrict__ b_h,
                const float* __restrict__ Wr_h, const float* __restrict__ Wz_h,
                const float* __restrict__ Wh_h)
{
    extern __shared__ float smem[];
    float* sA   = smem;                         // [k][c] -> {wr,wr,wz,wz}   (128 KB)
    float* sB   = sA + HID * CPC * 4;           // [k][c] -> {wh,wh}         (64 KB)
    float* z_s  = sB + HID * CPC * 2;           // z gate cache [c][b]       (2 KB)
    float* red  = z_s + CPC * Bsz;              // k-split reduction buffer  (8 KB)
    int*   tok  = (int*)(red + 2048);           // tokens for this step
    float* bias = (float*)(tok + Bsz);          // b_r | b_z | b_h (8 each)

    const int tid = threadIdx.x;
    const int cb  = blockIdx.x;
    const int c0  = cb * CPC;

    // ---- preload weight slices into smem in duplicated-pair layout ----
    for (int idx = tid; idx < HID * CPC; idx += NTHR) {
        int k = idx / CPC, c = idx % CPC;
        float wr = Wr_h[k * HID + c0 + c];
        float wz = Wz_h[k * HID + c0 + c];
        float wh = Wh_h[k * HID + c0 + c];
        sA[idx * 4 + 0] = wr; sA[idx * 4 + 1] = wr;
        sA[idx * 4 + 2] = wz; sA[idx * 4 + 3] = wz;
        sB[idx * 2 + 0] = wh; sB[idx * 2 + 1] = wh;
    }
    if (tid < CPC)          bias[tid] = b_r[c0 + tid];
    else if (tid < 2 * CPC) bias[tid] = b_z[c0 + tid - CPC];
    else if (tid < 3 * CPC) bias[tid] = b_h[c0 + tid - 2 * CPC];

    // zero this CTA's columns of h (h0 = 0); must be re-done every launch
    for (int idx = tid; idx < CPC * Bsz; idx += NTHR)
        g_hT[(c0 + idx / Bsz) * Bsz + (idx % Bsz)] = 0.0f;

    gbar();

    // GEMM thread mapping: k-split in 2 groups, each 16 bq x 8 c threads,
    // each thread accumulates 4 batch rows (two f32x2 pairs) for its column.
    const int kg    = tid >> 7;           // 0..1  (k half)
    const int r128  = tid & 127;
    const int bq    = r128 >> 3;          // 0..15 (batch quad)
    const int c     = r128 & 7;           // 0..7  (column within CTA)
    const int kbase = kg * (HID / 2);

    // postproc mapping: 32 batch-pairs x 8 cols
    const int bp    = tid >> 3;           // 0..31
    const int cpp   = tid & 7;
    const int cc_pp = c0 + cpp;

    for (int t = 0; t < Tlen; ++t) {
        if (tid < Bsz) tok[tid] = X[tid * Tlen + t];
        __syncthreads();

        // ======================= Phase A: r,z = h @ [Wr_h|Wz_h] ================
        unsigned long long aR0 = 0, aR1 = 0, aZ0 = 0, aZ1 = 0;
        {
            const float* hp = g_hT + kbase * Bsz + bq * 4;
            const float* wp = sA + (kbase * CPC + c) * 4;
            ulonglong2 buf[2][8];
            #pragma unroll
            for (int u = 0; u < 8; ++u) buf[0][u] = ldg_cg_u2(hp + u * Bsz);
            #pragma unroll 1
            for (int blk = 0; blk < (HID / 2) / 8; ++blk) {
                const int cur = blk & 1;
                if (blk + 1 < (HID / 2) / 8) {
                    const float* hpn = hp + (blk + 1) * 8 * Bsz;
                    #pragma unroll
                    for (int u = 0; u < 8; ++u)
                        buf[cur ^ 1][u] = ldg_cg_u2(hpn + u * Bsz);
                }
                const float* wpb = wp + blk * 8 * CPC * 4;
                #pragma unroll
                for (int u = 0; u < 8; ++u) {
                    ulonglong2 w  = *(const ulonglong2*)(wpb + u * CPC * 4);
                    ulonglong2 hv = buf[cur][u];
                    ffma2(aR0, hv.x, w.x);
                    ffma2(aR1, hv.y, w.x);
                    ffma2(aZ0, hv.x, w.y);
                    ffma2(aZ1, hv.y, w.y);
                }
            }
        }
        {   // write k-split partials: red[((kg*B + b)*CPC + c)*2 + {r,z}]
            float r0, r1, r2, r3, z0, z1, z2, z3;
            unpack2(aR0, r0, r1); unpack2(aR1, r2, r3);
            unpack2(aZ0, z0, z1); unpack2(aZ1, z2, z3);
            float* rp = red + ((kg * Bsz + bq * 4) * CPC + c) * 2;
            rp[0] = r0; rp[1] = z0; rp += CPC * 2;
            rp[0] = r1; rp[1] = z1; rp += CPC * 2;
            rp[0] = r2; rp[1] = z2; rp += CPC * 2;
            rp[0] = r3; rp[1] = z3;
        }
        __syncthreads();
        {   // gates + r*h for this CTA's columns
            #pragma unroll
            for (int j = 0; j < 2; ++j) {
                int b = bp * 2 + j;
                float sR = red[(b * CPC + cpp) * 2 + 0] +
                           red[((Bsz + b) * CPC + cpp) * 2 + 0];
                float sZ = red[(b * CPC + cpp) * 2 + 1] +
                           red[((Bsz + b) * CPC + cpp) * 2 + 1];
                int tk = tok[b];
                float rv = sigmoidf_(sR + __ldg(&Wr_x[tk * HID + cc_pp]) + bias[cpp]);
                float zv = sigmoidf_(sZ + __ldg(&Wz_x[tk * HID + cc_pp]) + bias[CPC + cpp]);
                float hold = g_hT[cc_pp * Bsz + b];
                z_s[cpp * Bsz + b]  = zv;
                g_rhT[cc_pp * Bsz + b] = rv * hold;
            }
        }
        gbar();

        // ======================= Phase B: htilde = (r*h) @ Wh_h ================
        unsigned long long aH0 = 0, aH1 = 0;
        {
            const float* hp = g_rhT + kbase * Bsz + bq * 4;
            const float* wp = sB + (kbase * CPC + c) * 2;
            ulonglong2 buf[2][8];
            #pragma unroll
            for (int u = 0; u < 8; ++u) buf[0][u] = ldg_cg_u2(hp + u * Bsz);
            #pragma unroll 1
            for (int blk = 0; blk < (HID / 2) / 8; ++blk) {
                const int cur = blk & 1;
                if (blk + 1 < (HID / 2) / 8) {
                    const float* hpn = hp + (blk + 1) * 8 * Bsz;
                    #pragma unroll
                    for (int u = 0; u < 8; ++u)
                        buf[cur ^ 1][u] = ldg_cg_u2(hpn + u * Bsz);
                }
                const float* wpb = wp + blk * 8 * CPC * 2;
                #pragma unroll
                for (int u = 0; u < 8; ++u) {
                    unsigned long long w = *(const unsigned long long*)(wpb + u * CPC * 2);
                    ulonglong2 hv = buf[cur][u];
                    ffma2(aH0, hv.x, w);
                    ffma2(aH1, hv.y, w);
                }
            }
        }
        {
            float h0, h1, h2, h3;
            unpack2(aH0, h0, h1); unpack2(aH1, h2, h3);
            float* rp = red + (kg * Bsz + bq * 4) * CPC + c;
            rp[0] = h0; rp[CPC] = h1; rp[2 * CPC] = h2; rp[3 * CPC] = h3;
        }
        __syncthreads();
        {   // h update + history write
            #pragma unroll
            for (int j = 0; j < 2; ++j) {
                int b = bp * 2 + j;
                float sH = red[b * CPC + cpp] + red[(Bsz + b) * CPC + cpp];
                int tk = tok[b];
                float ht = tanhf(sH + __ldg(&Wh_x[tk * HID + cc_pp]) + bias[2 * CPC + cpp]);
                float zv = z_s[cpp * Bsz + b];
                float hold = g_hT[cc_pp * Bsz + b];
                float hn = zv * hold + (1.0f - zv) * ht;
                g_hT[cc_pp * Bsz + b] = hn;
                g_hist[((size_t)t * HID + cc_pp) * Bsz + b] = hn;
            }
        }
        gbar();
    }
}

// ---------------- output head: out[b][t][v] = hist[t][:][b] . W_o[:,v] + b_o ---
#define KC 128
__global__ void __launch_bounds__(256)
head_kernel(const float* __restrict__ W_o, const float* __restrict__ b_o,
            float* __restrict__ out)
{
    extern __shared__ float swo[];          // KC x VOC chunk of W_o (64 KB)
    const int t   = blockIdx.x;
    const int tid = threadIdx.x;
    const int b   = tid >> 2;               // 0..63
    const int v0  = (tid & 3) * 32;         // 32 vocab cols per thread

    unsigned long long acc[16];
    #pragma unroll
    for (int i = 0; i < 16; ++i) acc[i] = 0ull;

    for (int kc = 0; kc < HID; kc += KC) {
        __syncthreads();
        for (int i = tid; i < KC * VOC; i += 256)
            swo[i] = W_o[kc * VOC + i];
        __syncthreads();

        const float* hp = g_hist + ((size_t)t * HID + kc) * Bsz + b;
        #pragma unroll 1
        for (int kk = 0; kk < KC; kk += 8) {
            float hv[8];
            #pragma unroll
            for (int u = 0; u < 8; ++u) hv[u] = __ldcg(hp + (kk + u) * Bsz);
            #pragma unroll
            for (int u = 0; u < 8; ++u) {
                unsigned long long hs;
                asm("mov.b64 %0, {%1, %1};" : "=l"(hs) : "f"(hv[u]));
                const float* wrow = swo + (kk + u) * VOC + v0;
                #pragma unroll
                for (int q = 0; q < 8; ++q) {
                    ulonglong2 w = *(const ulonglong2*)(wrow + q * 4);
                    ffma2(acc[q * 2 + 0], hs, w.x);
                    ffma2(acc[q * 2 + 1], hs, w.y);
                }
            }
        }
    }

    float* op = out + ((size_t)b * Tlen + t) * VOC + v0;
    #pragma unroll
    for (int q = 0; q < 16; ++q) {
        float lo, hi;
        unpack2(acc[q], lo, hi);
        int v = v0 + q * 2;
        op[q * 2 + 0] = lo + b_o[v + 0];
        op[q * 2 + 1] = hi + b_o[v + 1];
    }
}

// ---------------- launch ------------------------------------------------------
extern "C" void kernel_launch(void* const* d_in, const int* in_sizes, int n_in,
                              void* d_out, int out_size)
{
    const int*   X    = (const int*)  d_in[0];
    const float* Wr_x = (const float*)d_in[1];
    const float* Wr_h = (const float*)d_in[2];
    const float* b_r  = (const float*)d_in[3];
    const float* Wz_x = (const float*)d_in[4];
    const float* Wz_h = (const float*)d_in[5];
    const float* b_z  = (const float*)d_in[6];
    const float* Wh_x = (const float*)d_in[7];
    const float* Wh_h = (const float*)d_in[8];
    const float* b_h  = (const float*)d_in[9];
    const float* W_o  = (const float*)d_in[10];
    const float* b_o  = (const float*)d_in[11];
    float* out = (float*)d_out;

    size_t smem1 = (size_t)(HID * CPC * 4 + HID * CPC * 2 + CPC * Bsz + 2048) * sizeof(float)
                 + Bsz * sizeof(int) + 32 * sizeof(float);
    size_t smem2 = (size_t)KC * VOC * sizeof(float);

    cudaFuncSetAttribute(gru_step_kernel,
                         cudaFuncAttributeMaxDynamicSharedMemorySize, (int)smem1);
    cudaFuncSetAttribute(head_kernel,
                         cudaFuncAttributeMaxDynamicSharedMemorySize, (int)smem2);

    gru_step_kernel<<<GRID, NTHR, smem1>>>(X, Wr_x, b_r, Wz_x, b_z, Wh_x, b_h,
                                           Wr_h, Wz_h, Wh_h);
    head_kernel<<<Tlen, 256, smem2>>>(W_o, b_o, out);
}

// round 2
// speedup vs baseline: 2.4565x; 2.4565x over previous
#include <cuda_runtime.h>
#include <cstdint>
#include <cstddef>

#define Bsz   64
#define Tlen  512
#define HID   1024
#define VOC   128
#define GRID  128
#define CPC   8          // hidden columns owned per CTA
#define NTHR  256

// ---------------- persistent device scratch (no allocations allowed) ----------
__device__ float g_hT[HID * Bsz];                       // h, transposed [k][b]
__device__ float g_rhT[HID * Bsz];                      // r*h, transposed [k][b]
__device__ float g_hist[(size_t)Tlen * HID * Bsz];      // [t][k][b]  (134 MB)
__device__ unsigned g_cnt = 0;
__device__ volatile unsigned g_gen = 0;

// ---------------- helpers -----------------------------------------------------
__device__ __forceinline__ void ffma2(unsigned long long &acc,
                                      unsigned long long a,
                                      unsigned long long b) {
    asm volatile("fma.rn.f32x2 %0, %1, %2, %0;" : "+l"(acc) : "l"(a), "l"(b));
}

__device__ __forceinline__ ulonglong2 ldg_cg_u2(const float* p) {
    ulonglong2 r;
    asm volatile("ld.global.cg.v2.u64 {%0, %1}, [%2];"
                 : "=l"(r.x), "=l"(r.y) : "l"(p));
    return r;
}

__device__ __forceinline__ void unpack2(unsigned long long v, float &lo, float &hi) {
    asm("mov.b64 {%0, %1}, %2;" : "=f"(lo), "=f"(hi) : "l"(v));
}

__device__ __forceinline__ float sigmoidf_(float x) {
    return 1.0f / (1.0f + __expf(-x));
}

// grid-wide sense-reversal barrier; the gpu-scope fences also flush L1D
// so plain loads after the barrier see other CTAs' stores.
__device__ __forceinline__ void gbar() {
    __syncthreads();
    if (threadIdx.x == 0) {
        unsigned g = g_gen;
        __threadfence();
        unsigned a = atomicAdd(&g_cnt, 1u);
        if (a == GRID - 1) {
            g_cnt = 0;
            __threadfence();
            g_gen = g + 1;
        } else {
            while (g_gen == g) { }
            __threadfence();
        }
    }
    __syncthreads();
}

// ---------------- persistent GRU recurrence kernel -----------------------------
__global__ void __launch_bounds__(NTHR, 1)
gru_step_kernel(const int* __restrict__ X,
                const float* __restrict__ Wr_x, const float* __restrict__ b_r,
                const float* __restrict__ Wz_x, const float* __restrict__ b_z,
                const float* __restrict__ Wh_x, const float* __restrict__ b_h,
                const float* __restrict__ Wr_h, const float* __restrict__ Wz_h,
                const float* __restrict__ Wh_h)
{
    extern __shared__ float smem[];
    float* sA   = smem;                         // [k][c] -> {wr,wr,wz,wz}   (128 KB)
    float* sB   = sA + HID * CPC * 4;           // [k][c] -> {wh,wh}         (64 KB)
    float* z_s  = sB + HID * CPC * 2;           // z gate cache [c][b]       (2 KB)
    float* red  = z_s + CPC * Bsz;              // k-split reduction buffer  (8 KB)
    int*   tok  = (int*)(red + 2048);           // tokens for this step
    float* bias = (float*)(tok + Bsz);          // b_r | b_z | b_h (8 each)

    const int tid = threadIdx.x;
    const int cb  = blockIdx.x;
    const int c0  = cb * CPC;

    // ---- preload weight slices into smem in duplicated-pair layout ----
    for (int idx = tid; idx < HID * CPC; idx += NTHR) {
        int k = idx / CPC, c = idx % CPC;
        float wr = Wr_h[k * HID + c0 + c];
        float wz = Wz_h[k * HID + c0 + c];
        float wh = Wh_h[k * HID + c0 + c];
        sA[idx * 4 + 0] = wr; sA[idx * 4 + 1] = wr;
        sA[idx * 4 + 2] = wz; sA[idx * 4 + 3] = wz;
        sB[idx * 2 + 0] = wh; sB[idx * 2 + 1] = wh;
    }
    if (tid < CPC)          bias[tid] = b_r[c0 + tid];
    else if (tid < 2 * CPC) bias[tid] = b_z[c0 + tid - CPC];
    else if (tid < 3 * CPC) bias[tid] = b_h[c0 + tid - 2 * CPC];

    // zero this CTA's columns of h (h0 = 0); must be re-done every launch
    for (int idx = tid; idx < CPC * Bsz; idx += NTHR)
        g_hT[(c0 + idx / Bsz) * Bsz + (idx % Bsz)] = 0.0f;

    gbar();

    // GEMM thread mapping: k-split in 2 groups, each 16 bq x 8 c threads,
    // each thread accumulates 4 batch rows (two f32x2 pairs) for its column.
    const int kg    = tid >> 7;           // 0..1  (k half)
    const int r128  = tid & 127;
    const int bq    = r128 >> 3;          // 0..15 (batch quad)
    const int c     = r128 & 7;           // 0..7  (column within CTA)
    const int kbase = kg * (HID / 2);

    // postproc mapping: 32 batch-pairs x 8 cols
    const int bp    = tid >> 3;           // 0..31
    const int cpp   = tid & 7;
    const int cc_pp = c0 + cpp;

    for (int t = 0; t < Tlen; ++t) {
        if (tid < Bsz) tok[tid] = X[tid * Tlen + t];
        __syncthreads();

        // ======================= Phase A: r,z = h @ [Wr_h|Wz_h] ================
        unsigned long long aR0 = 0, aR1 = 0, aZ0 = 0, aZ1 = 0;
        {
            const float* hp = g_hT + kbase * Bsz + bq * 4;
            const float* wp = sA + (kbase * CPC + c) * 4;
            ulonglong2 b0[8], b1[8];
            #pragma unroll
            for (int u = 0; u < 8; ++u) b0[u] = ldg_cg_u2(hp + u * Bsz);
            #pragma unroll 1
            for (int blk = 0; blk < 64; blk += 2) {
                // prefetch blk+1 into b1 (always in range: blk <= 62)
                {
                    const float* hpn = hp + (blk + 1) * 8 * Bsz;
                    #pragma unroll
                    for (int u = 0; u < 8; ++u) b1[u] = ldg_cg_u2(hpn + u * Bsz);
                }
                // consume blk from b0
                {
                    const float* wpb = wp + blk * 8 * CPC * 4;
                    #pragma unroll
                    for (int u = 0; u < 8; ++u) {
                        ulonglong2 w = *(const ulonglong2*)(wpb + u * CPC * 4);
                        ffma2(aR0, b0[u].x, w.x);
                        ffma2(aR1, b0[u].y, w.x);
                        ffma2(aZ0, b0[u].x, w.y);
                        ffma2(aZ1, b0[u].y, w.y);
                    }
                }
                // prefetch blk+2 into b0 (guarded; predicated loads)
                if (blk + 2 < 64) {
                    const float* hpn = hp + (blk + 2) * 8 * Bsz;
                    #pragma unroll
                    for (int u = 0; u < 8; ++u) b0[u] = ldg_cg_u2(hpn + u * Bsz);
                }
                // consume blk+1 from b1
                {
                    const float* wpb = wp + (blk + 1) * 8 * CPC * 4;
                    #pragma unroll
                    for (int u = 0; u < 8; ++u) {
                        ulonglong2 w = *(const ulonglong2*)(wpb + u * CPC * 4);
                        ffma2(aR0, b1[u].x, w.x);
                        ffma2(aR1, b1[u].y, w.x);
                        ffma2(aZ0, b1[u].x, w.y);
                        ffma2(aZ1, b1[u].y, w.y);
                    }
                }
            }
        }
        {   // write k-split partials: red[((kg*B + b)*CPC + c)*2 + {r,z}]
            float r0, r1, r2, r3, z0, z1, z2, z3;
            unpack2(aR0, r0, r1); unpack2(aR1, r2, r3);
            unpack2(aZ0, z0, z1); unpack2(aZ1, z2, z3);
            float* rp = red + ((kg * Bsz + bq * 4) * CPC + c) * 2;
            rp[0] = r0; rp[1] = z0; rp += CPC * 2;
            rp[0] = r1; rp[1] = z1; rp += CPC * 2;
            rp[0] = r2; rp[1] = z2; rp += CPC * 2;
            rp[0] = r3; rp[1] = z3;
        }
        __syncthreads();
        {   // gates + r*h for this CTA's columns
            #pragma unroll
            for (int j = 0; j < 2; ++j) {
                int b = bp * 2 + j;
                float sR = red[(b * CPC + cpp) * 2 + 0] +
                           red[((Bsz + b) * CPC + cpp) * 2 + 0];
                float sZ = red[(b * CPC + cpp) * 2 + 1] +
                           red[((Bsz + b) * CPC + cpp) * 2 + 1];
                int tk = tok[b];
                float rv = sigmoidf_(sR + __ldg(&Wr_x[tk * HID + cc_pp]) + bias[cpp]);
                float zv = sigmoidf_(sZ + __ldg(&Wz_x[tk * HID + cc_pp]) + bias[CPC + cpp]);
                float hold = g_hT[cc_pp * Bsz + b];
                z_s[cpp * Bsz + b]  = zv;
                g_rhT[cc_pp * Bsz + b] = rv * hold;
            }
        }
        gbar();

        // ======================= Phase B: htilde = (r*h) @ Wh_h ================
        unsigned long long aH0 = 0, aH1 = 0;
        {
            const float* hp = g_rhT + kbase * Bsz + bq * 4;
            const float* wp = sB + (kbase * CPC + c) * 2;
            ulonglong2 b0[8], b1[8];
            #pragma unroll
            for (int u = 0; u < 8; ++u) b0[u] = ldg_cg_u2(hp + u * Bsz);
            #pragma unroll 1
            for (int blk = 0; blk < 64; blk += 2) {
                {
                    const float* hpn = hp + (blk + 1) * 8 * Bsz;
                    #pragma unroll
                    for (int u = 0; u < 8; ++u) b1[u] = ldg_cg_u2(hpn + u * Bsz);
                }
                {
                    const float* wpb = wp + blk * 8 * CPC * 2;
                    #pragma unroll
                    for (int u = 0; u < 8; ++u) {
                        unsigned long long w =
                            *(const unsigned long long*)(wpb + u * CPC * 2);
                        ffma2(aH0, b0[u].x, w);
                        ffma2(aH1, b0[u].y, w);
                    }
                }
                if (blk + 2 < 64) {
                    const float* hpn = hp + (blk + 2) * 8 * Bsz;
                    #pragma unroll
                    for (int u = 0; u < 8; ++u) b0[u] = ldg_cg_u2(hpn + u * Bsz);
                }
                {
                    const float* wpb = wp + (blk + 1) * 8 * CPC * 2;
                    #pragma unroll
                    for (int u = 0; u < 8; ++u) {
                        unsigned long long w =
                            *(const unsigned long long*)(wpb + u * CPC * 2);
                        ffma2(aH0, b1[u].x, w);
                        ffma2(aH1, b1[u].y, w);
                    }
                }
            }
        }
        {
            float h0, h1, h2, h3;
            unpack2(aH0, h0, h1); unpack2(aH1, h2, h3);
            float* rp = red + (kg * Bsz + bq * 4) * CPC + c;
            rp[0] = h0; rp[CPC] = h1; rp[2 * CPC] = h2; rp[3 * CPC] = h3;
        }
        __syncthreads();
        {   // h update + history write
            #pragma unroll
            for (int j = 0; j < 2; ++j) {
                int b = bp * 2 + j;
                float sH = red[b * CPC + cpp] + red[(Bsz + b) * CPC + cpp];
                int tk = tok[b];
                float ht = tanhf(sH + __ldg(&Wh_x[tk * HID + cc_pp]) + bias[2 * CPC + cpp]);
                float zv = z_s[cpp * Bsz + b];
                float hold = g_hT[cc_pp * Bsz + b];
                float hn = zv * hold + (1.0f - zv) * ht;
                g_hT[cc_pp * Bsz + b] = hn;
                g_hist[((size_t)t * HID + cc_pp) * Bsz + b] = hn;
            }
        }
        gbar();
    }
}

// ---------------- output head: out[b][t][v] = hist[t][:][b] . W_o[:,v] + b_o ---
#define KC 128
__global__ void __launch_bounds__(256)
head_kernel(const float* __restrict__ W_o, const float* __restrict__ b_o,
            float* __restrict__ out)
{
    extern __shared__ float swo[];          // KC x VOC chunk of W_o (64 KB)
    const int t   = blockIdx.x;
    const int tid = threadIdx.x;
    const int b   = tid >> 2;               // 0..63
    const int v0  = (tid & 3) * 32;         // 32 vocab cols per thread

    unsigned long long acc[16];
    #pragma unroll
    for (int i = 0; i < 16; ++i) acc[i] = 0ull;

    for (int kc = 0; kc < HID; kc += KC) {
        __syncthreads();
        for (int i = tid; i < KC * VOC; i += 256)
            swo[i] = W_o[kc * VOC + i];
        __syncthreads();

        const float* hp = g_hist + ((size_t)t * HID + kc) * Bsz + b;
        #pragma unroll 1
        for (int kk = 0; kk < KC; kk += 8) {
            float hv[8];
            #pragma unroll
            for (int u = 0; u < 8; ++u) hv[u] = __ldcg(hp + (kk + u) * Bsz);
            #pragma unroll
            for (int u = 0; u < 8; ++u) {
                unsigned long long hs;
                asm("mov.b64 %0, {%1, %1};" : "=l"(hs) : "f"(hv[u]));
                const float* wrow = swo + (kk + u) * VOC + v0;
                #pragma unroll
                for (int q = 0; q < 8; ++q) {
                    ulonglong2 w = *(const ulonglong2*)(wrow + q * 4);
                    ffma2(acc[q * 2 + 0], hs, w.x);
                    ffma2(acc[q * 2 + 1], hs, w.y);
                }
            }
        }
    }

    float* op = out + ((size_t)b * Tlen + t) * VOC + v0;
    #pragma unroll
    for (int q = 0; q < 16; ++q) {
        float lo, hi;
        unpack2(acc[q], lo, hi);
        int v = v0 + q * 2;
        op[q * 2 + 0] = lo + b_o[v + 0];
        op[q * 2 + 1] = hi + b_o[v + 1];
    }
}

// ---------------- launch ------------------------------------------------------
extern "C" void kernel_launch(void* const* d_in, const int* in_sizes, int n_in,
                              void* d_out, int out_size)
{
    const int*   X    = (const int*)  d_in[0];
    const float* Wr_x = (const float*)d_in[1];
    const float* Wr_h = (const float*)d_in[2];
    const float* b_r  = (const float*)d_in[3];
    const float* Wz_x = (const float*)d_in[4];
    const float* Wz_h = (const float*)d_in[5];
    const float* b_z  = (const float*)d_in[6];
    const float* Wh_x = (const float*)d_in[7];
    const float* Wh_h = (const float*)d_in[8];
    const float* b_h  = (const float*)d_in[9];
    const float* W_o  = (const float*)d_in[10];
    const float* b_o  = (const float*)d_in[11];
    float* out = (float*)d_out;

    size_t smem1 = (size_t)(HID * CPC * 4 + HID * CPC * 2 + CPC * Bsz + 2048) * sizeof(float)
                 + Bsz * sizeof(int) + 32 * sizeof(float);
    size_t smem2 = (size_t)KC * VOC * sizeof(float);

    cudaFuncSetAttribute(gru_step_kernel,
                         cudaFuncAttributeMaxDynamicSharedMemorySize, (int)smem1);
    cudaFuncSetAttribute(head_kernel,
                         cudaFuncAttributeMaxDynamicSharedMemorySize, (int)smem2);

    gru_step_kernel<<<GRID, NTHR, smem1>>>(X, Wr_x, b_r, Wz_x, b_z, Wh_x, b_h,
                                           Wr_h, Wz_h, Wh_h);
    head_kernel<<<Tlen, 256, smem2>>>(W_o, b_o, out);
}

// round 3
// speedup vs baseline: 2.8125x; 1.1449x over previous
#include <cuda_runtime.h>
#include <cstdint>
#include <cstddef>

#define Bsz   64
#define Tlen  512
#define HID   1024
#define VOC   128
#define GRID  128
#define CPC   8          // hidden columns owned per CTA
#define NTHR  256

// ---------------- persistent device scratch (no allocations allowed) ----------
__device__ float g_hT[HID * Bsz];                       // h, transposed [k][b]
__device__ float g_rhT[HID * Bsz];                      // r*h, transposed [k][b]
__device__ float g_hist[(size_t)Tlen * HID * Bsz];      // [t][k][b]  (134 MB)
__device__ unsigned g_cnt = 0;
__device__ volatile unsigned g_gen = 0;

// ---------------- helpers -----------------------------------------------------
__device__ __forceinline__ void ffma2(unsigned long long &acc,
                                      unsigned long long a,
                                      unsigned long long b) {
    asm volatile("fma.rn.f32x2 %0, %1, %2, %0;" : "+l"(acc) : "l"(a), "l"(b));
}

__device__ __forceinline__ ulonglong2 ldg_cg_u2(const float* p) {
    ulonglong2 r;
    asm volatile("ld.global.cg.v2.u64 {%0, %1}, [%2];"
                 : "=l"(r.x), "=l"(r.y) : "l"(p));
    return r;
}

__device__ __forceinline__ void unpack2(unsigned long long v, float &lo, float &hi) {
    asm("mov.b64 {%0, %1}, %2;" : "=f"(lo), "=f"(hi) : "l"(v));
}

__device__ __forceinline__ float sigmoidf_(float x) {
    return 1.0f / (1.0f + __expf(-x));
}

__device__ __forceinline__ int imin_(int a, int b) { return a < b ? a : b; }

// grid-wide sense-reversal barrier
__device__ __forceinline__ void gbar() {
    __syncthreads();
    if (threadIdx.x == 0) {
        unsigned g = g_gen;
        __threadfence();
        unsigned a = atomicAdd(&g_cnt, 1u);
        if (a == GRID - 1) {
            g_cnt = 0;
            __threadfence();
            g_gen = g + 1;
        } else {
            while (g_gen == g) { }
            __threadfence();
        }
    }
    __syncthreads();
}

// ---------------- persistent GRU recurrence kernel -----------------------------
__global__ void __launch_bounds__(NTHR, 1)
gru_step_kernel(const int* __restrict__ X,
                const float* __restrict__ Wr_x, const float* __restrict__ b_r,
                const float* __restrict__ Wz_x, const float* __restrict__ b_z,
                const float* __restrict__ Wh_x, const float* __restrict__ b_h,
                const float* __restrict__ Wr_h, const float* __restrict__ Wz_h,
                const float* __restrict__ Wh_h)
{
    extern __shared__ float smem[];
    float* sA   = smem;                         // [k][c] -> {wr,wr,wz,wz}   (128 KB)
    float* sB   = sA + HID * CPC * 4;           // [k][c] -> {wh,wh}         (64 KB)
    float* z_s  = sB + HID * CPC * 2;           // z gate cache [c][b]       (2 KB)
    float* red  = z_s + CPC * Bsz;              // k-split reduction buffer  (8 KB)
    int*   tok  = (int*)(red + 2048);           // tokens for this step
    float* bias = (float*)(tok + Bsz);          // b_r | b_z | b_h (8 each)

    const int tid = threadIdx.x;
    const int cb  = blockIdx.x;
    const int c0  = cb * CPC;

    // ---- preload weight slices into smem in duplicated-pair layout ----
    for (int idx = tid; idx < HID * CPC; idx += NTHR) {
        int k = idx / CPC, c = idx % CPC;
        float wr = Wr_h[k * HID + c0 + c];
        float wz = Wz_h[k * HID + c0 + c];
        float wh = Wh_h[k * HID + c0 + c];
        sA[idx * 4 + 0] = wr; sA[idx * 4 + 1] = wr;
        sA[idx * 4 + 2] = wz; sA[idx * 4 + 3] = wz;
        sB[idx * 2 + 0] = wh; sB[idx * 2 + 1] = wh;
    }
    if (tid < CPC)          bias[tid] = b_r[c0 + tid];
    else if (tid < 2 * CPC) bias[tid] = b_z[c0 + tid - CPC];
    else if (tid < 3 * CPC) bias[tid] = b_h[c0 + tid - 2 * CPC];

    // zero this CTA's columns of h (h0 = 0); must be re-done every launch
    for (int idx = tid; idx < CPC * Bsz; idx += NTHR)
        g_hT[(c0 + idx / Bsz) * Bsz + (idx % Bsz)] = 0.0f;

    gbar();

    // GEMM thread mapping: k-split in 2 groups, each 16 bq x 8 c threads,
    // each thread accumulates 4 batch rows (two f32x2 pairs) for its column.
    const int kg    = tid >> 7;           // 0..1  (k half)
    const int r128  = tid & 127;
    const int bq    = r128 >> 3;          // 0..15 (batch quad)
    const int c     = r128 & 7;           // 0..7  (column within CTA)
    const int kbase = kg * (HID / 2);

    // postproc mapping: 32 batch-pairs x 8 cols
    const int bp    = tid >> 3;           // 0..31
    const int cpp   = tid & 7;
    const int cc_pp = c0 + cpp;

    for (int t = 0; t < Tlen; ++t) {
        if (tid < Bsz) tok[tid] = X[tid * Tlen + t];
        __syncthreads();

        // ======================= Phase A: r,z = h @ [Wr_h|Wz_h] ================
        // 64 stages of 8 k-values; 4 register buffers, 3-stage lookahead.
        unsigned long long aR0 = 0, aR1 = 0, aZ0 = 0, aZ1 = 0;
        {
            const float* hp = g_hT + kbase * Bsz + bq * 4;
            const float* wp = sA + (kbase * CPC + c) * 4;
            ulonglong2 B0[8], B1[8], B2[8], B3[8];

            #pragma unroll
            for (int u = 0; u < 8; ++u) B0[u] = ldg_cg_u2(hp + (0 * 8 + u) * Bsz);
            #pragma unroll
            for (int u = 0; u < 8; ++u) B1[u] = ldg_cg_u2(hp + (1 * 8 + u) * Bsz);
            #pragma unroll
            for (int u = 0; u < 8; ++u) B2[u] = ldg_cg_u2(hp + (2 * 8 + u) * Bsz);

            #define A_PF(BUF, S)                                                   \
                {   int s_ = imin_((S), 63);                                       \
                    const float* hpn = hp + s_ * 8 * Bsz;                          \
                    _Pragma("unroll")                                              \
                    for (int u = 0; u < 8; ++u) BUF[u] = ldg_cg_u2(hpn + u * Bsz); }
            #define A_CONS(BUF, S)                                                 \
                {   const float* wpb = wp + (S) * 8 * CPC * 4;                     \
                    _Pragma("unroll")                                              \
                    for (int u = 0; u < 8; ++u) {                                  \
                        ulonglong2 w = *(const ulonglong2*)(wpb + u * CPC * 4);    \
                        ffma2(aR0, BUF[u].x, w.x);                                 \
                        ffma2(aR1, BUF[u].y, w.x);                                 \
                        ffma2(aZ0, BUF[u].x, w.y);                                 \
                        ffma2(aZ1, BUF[u].y, w.y);                                 \
                    } }

            #pragma unroll 1
            for (int blk = 0; blk < 64; blk += 4) {
                A_PF(B3, blk + 3)
                A_CONS(B0, blk + 0)
                A_PF(B0, blk + 4)
                A_CONS(B1, blk + 1)
                A_PF(B1, blk + 5)
                A_CONS(B2, blk + 2)
                A_PF(B2, blk + 6)
                A_CONS(B3, blk + 3)
            }
            #undef A_PF
            #undef A_CONS
        }
        {   // write k-split partials: red[((kg*B + b)*CPC + c)*2 + {r,z}]
            float r0, r1, r2, r3, z0, z1, z2, z3;
            unpack2(aR0, r0, r1); unpack2(aR1, r2, r3);
            unpack2(aZ0, z0, z1); unpack2(aZ1, z2, z3);
            float* rp = red + ((kg * Bsz + bq * 4) * CPC + c) * 2;
            rp[0] = r0; rp[1] = z0; rp += CPC * 2;
            rp[0] = r1; rp[1] = z1; rp += CPC * 2;
            rp[0] = r2; rp[1] = z2; rp += CPC * 2;
            rp[0] = r3; rp[1] = z3;
        }
        __syncthreads();
        {   // gates + r*h for this CTA's columns
            #pragma unroll
            for (int j = 0; j < 2; ++j) {
                int b = bp * 2 + j;
                float sR = red[(b * CPC + cpp) * 2 + 0] +
                           red[((Bsz + b) * CPC + cpp) * 2 + 0];
                float sZ = red[(b * CPC + cpp) * 2 + 1] +
                           red[((Bsz + b) * CPC + cpp) * 2 + 1];
                int tk = tok[b];
                float rv = sigmoidf_(sR + __ldg(&Wr_x[tk * HID + cc_pp]) + bias[cpp]);
                float zv = sigmoidf_(sZ + __ldg(&Wz_x[tk * HID + cc_pp]) + bias[CPC + cpp]);
                float hold = g_hT[cc_pp * Bsz + b];
                z_s[cpp * Bsz + b]  = zv;
                g_rhT[cc_pp * Bsz + b] = rv * hold;
            }
        }
        gbar();

        // ======================= Phase B: htilde = (r*h) @ Wh_h ================
        unsigned long long aH0 = 0, aH1 = 0;
        {
            const float* hp = g_rhT + kbase * Bsz + bq * 4;
            const float* wp = sB + (kbase * CPC + c) * 2;
            ulonglong2 B0[8], B1[8], B2[8], B3[8];

            #pragma unroll
            for (int u = 0; u < 8; ++u) B0[u] = ldg_cg_u2(hp + (0 * 8 + u) * Bsz);
            #pragma unroll
            for (int u = 0; u < 8; ++u) B1[u] = ldg_cg_u2(hp + (1 * 8 + u) * Bsz);
            #pragma unroll
            for (int u = 0; u < 8; ++u) B2[u] = ldg_cg_u2(hp + (2 * 8 + u) * Bsz);

            #define B_PF(BUF, S)                                                   \
                {   int s_ = imin_((S), 63);                                       \
                    const float* hpn = hp + s_ * 8 * Bsz;                          \
                    _Pragma("unroll")                                              \
                    for (int u = 0; u < 8; ++u) BUF[u] = ldg_cg_u2(hpn + u * Bsz); }
            #define B_CONS(BUF, S)                                                 \
                {   const float* wpb = wp + (S) * 8 * CPC * 2;                     \
                    _Pragma("unroll")                                              \
                    for (int u = 0; u < 8; ++u) {                                  \
                        unsigned long long w =                                     \
                            *(const unsigned long long*)(wpb + u * CPC * 2);       \
                        ffma2(aH0, BUF[u].x, w);                                   \
                        ffma2(aH1, BUF[u].y, w);                                   \
                    } }

            #pragma unroll 1
            for (int blk = 0; blk < 64; blk += 4) {
                B_PF(B3, blk + 3)
                B_CONS(B0, blk + 0)
                B_PF(B0, blk + 4)
                B_CONS(B1, blk + 1)
                B_PF(B1, blk + 5)
                B_CONS(B2, blk + 2)
                B_PF(B2, blk + 6)
                B_CONS(B3, blk + 3)
            }
            #undef B_PF
            #undef B_CONS
        }
        {
            float h0, h1, h2, h3;
            unpack2(aH0, h0, h1); unpack2(aH1, h2, h3);
            float* rp = red + (kg * Bsz + bq * 4) * CPC + c;
            rp[0] = h0; rp[CPC] = h1; rp[2 * CPC] = h2; rp[3 * CPC] = h3;
        }
        __syncthreads();
        {   // h update + history write
            #pragma unroll
            for (int j = 0; j < 2; ++j) {
                int b = bp * 2 + j;
                float sH = red[b * CPC + cpp] + red[(Bsz + b) * CPC + cpp];
                int tk = tok[b];
                float ht = tanhf(sH + __ldg(&Wh_x[tk * HID + cc_pp]) + bias[2 * CPC + cpp]);
                float zv = z_s[cpp * Bsz + b];
                float hold = g_hT[cc_pp * Bsz + b];
                float hn = zv * hold + (1.0f - zv) * ht;
                g_hT[cc_pp * Bsz + b] = hn;
                g_hist[((size_t)t * HID + cc_pp) * Bsz + b] = hn;
            }
        }
        gbar();
    }
}

// ---------------- output head: out[b][t][v] = hist[t][:][b] . W_o[:,v] + b_o ---
#define KC 128
__global__ void __launch_bounds__(256)
head_kernel(const float* __restrict__ W_o, const float* __restrict__ b_o,
            float* __restrict__ out)
{
    extern __shared__ float swo[];          // KC x VOC chunk of W_o (64 KB)
    const int t   = blockIdx.x;
    const int tid = threadIdx.x;
    const int b   = tid >> 2;               // 0..63
    const int v0  = (tid & 3) * 32;         // 32 vocab cols per thread

    unsigned long long acc[16];
    #pragma unroll
    for (int i = 0; i < 16; ++i) acc[i] = 0ull;

    for (int kc = 0; kc < HID; kc += KC) {
        __syncthreads();
        for (int i = tid; i < KC * VOC; i += 256)
            swo[i] = W_o[kc * VOC + i];
        __syncthreads();

        const float* hp = g_hist + ((size_t)t * HID + kc) * Bsz + b;
        #pragma unroll 1
        for (int kk = 0; kk < KC; kk += 8) {
            float hv[8];
            #pragma unroll
            for (int u = 0; u < 8; ++u) hv[u] = __ldcg(hp + (kk + u) * Bsz);
            #pragma unroll
            for (int u = 0; u < 8; ++u) {
                unsigned long long hs;
                asm("mov.b64 %0, {%1, %1};" : "=l"(hs) : "f"(hv[u]));
                const float* wrow = swo + (kk + u) * VOC + v0;
                #pragma unroll
                for (int q = 0; q < 8; ++q) {
                    ulonglong2 w = *(const ulonglong2*)(wrow + q * 4);
                    ffma2(acc[q * 2 + 0], hs, w.x);
                    ffma2(acc[q * 2 + 1], hs, w.y);
                }
            }
        }
    }

    float* op = out + ((size_t)b * Tlen + t) * VOC + v0;
    #pragma unroll
    for (int q = 0; q < 16; ++q) {
        float lo, hi;
        unpack2(acc[q], lo, hi);
        int v = v0 + q * 2;
        op[q * 2 + 0] = lo + b_o[v + 0];
        op[q * 2 + 1] = hi + b_o[v + 1];
    }
}

// ---------------- launch ------------------------------------------------------
extern "C" void kernel_launch(void* const* d_in, const int* in_sizes, int n_in,
                              void* d_out, int out_size)
{
    const int*   X    = (const int*)  d_in[0];
    const float* Wr_x = (const float*)d_in[1];
    const float* Wr_h = (const float*)d_in[2];
    const float* b_r  = (const float*)d_in[3];
    const float* Wz_x = (const float*)d_in[4];
    const float* Wz_h = (const float*)d_in[5];
    const float* b_z  = (const float*)d_in[6];
    const float* Wh_x = (const float*)d_in[7];
    const float* Wh_h = (const float*)d_in[8];
    const float* b_h  = (const float*)d_in[9];
    const float* W_o  = (const float*)d_in[10];
    const float* b_o  = (const float*)d_in[11];
    float* out = (float*)d_out;

    size_t smem1 = (size_t)(HID * CPC * 4 + HID * CPC * 2 + CPC * Bsz + 2048) * sizeof(float)
                 + Bsz * sizeof(int) + 32 * sizeof(float);
    size_t smem2 = (size_t)KC * VOC * sizeof(float);

    cudaFuncSetAttribute(gru_step_kernel,
                         cudaFuncAttributeMaxDynamicSharedMemorySize, (int)smem1);
    cudaFuncSetAttribute(head_kernel,
                         cudaFuncAttributeMaxDynamicSharedMemorySize, (int)smem2);

    gru_step_kernel<<<GRID, NTHR, smem1>>>(X, Wr_x, b_r, Wz_x, b_z, Wh_x, b_h,
                                           Wr_h, Wz_h, Wh_h);
    head_kernel<<<Tlen, 256, smem2>>>(W_o, b_o, out);
}

// round 4
// speedup vs baseline: 3.2140x; 1.1428x over previous
#include <cuda_runtime.h>
#include <cstdint>
#include <cstddef>

#define Bsz   64
#define Tlen  512
#define HID   1024
#define VOC   128
#define GRID  128
#define CPC   8          // hidden columns owned per CTA
#define NTHR  256
#define CHUNK_K 32       // k-rows per cp.async chunk
#define NCHUNK  16       // chunks per kg half (512/32)

// ---------------- persistent device scratch (no allocations allowed) ----------
__device__ float g_hT[HID * Bsz];                       // h, transposed [k][b]
__device__ float g_rhT[HID * Bsz];                      // r*h, transposed [k][b]
__device__ float g_hist[(size_t)Tlen * HID * Bsz];      // [t][k][b]  (134 MB)
__device__ unsigned g_flags[GRID];                      // barrier flags (zero-init)

// ---------------- helpers -----------------------------------------------------
__device__ __forceinline__ void ffma2(unsigned long long &acc,
                                      unsigned long long a,
                                      unsigned long long b) {
    asm volatile("fma.rn.f32x2 %0, %1, %2, %0;" : "+l"(acc) : "l"(a), "l"(b));
}

__device__ __forceinline__ void unpack2(unsigned long long v, float &lo, float &hi) {
    asm("mov.b64 {%0, %1}, %2;" : "=f"(lo), "=f"(hi) : "l"(v));
}

__device__ __forceinline__ float sigmoidf_(float x) {
    return 1.0f / (1.0f + __expf(-x));
}

// distributed-flag grid barrier: release-store own flag, acquire-poll all flags.
__device__ __forceinline__ void gbar(unsigned stamp) {
    __syncthreads();
    if (threadIdx.x == 0) {
        asm volatile("st.global.release.gpu.u32 [%0], %1;"
                     :: "l"(&g_flags[blockIdx.x]), "r"(stamp) : "memory");
    }
    if (threadIdx.x < GRID) {
        unsigned v;
        do {
            asm volatile("ld.global.acquire.gpu.u32 %0, [%1];"
                         : "=r"(v) : "l"(&g_flags[threadIdx.x]) : "memory");
        } while (v < stamp);
    }
    __syncthreads();
}

// copy one 8KB chunk (32 k-rows x 64 batch floats) gmem -> smem via cp.async.
// 128 threads of a kg group participate; 4 x 16B per thread.
__device__ __forceinline__ void copy_chunk(float* dst, const float* src, int r128) {
    uint32_t s = (uint32_t)__cvta_generic_to_shared(dst) + r128 * 16;
    const float* g = src + r128 * 4;
    #pragma unroll
    for (int i = 0; i < 4; ++i) {
        asm volatile("cp.async.cg.shared.global [%0], [%1], 16;"
                     :: "r"(s + i * 2048), "l"(g + i * 512) : "memory");
    }
    asm volatile("cp.async.commit_group;" ::: "memory");
}

__device__ __forceinline__ void wait_cp0() {
    asm volatile("cp.async.wait_group 0;" ::: "memory");
}

__device__ __forceinline__ void named_bar(int id) {
    asm volatile("bar.sync %0, 128;" :: "r"(id) : "memory");
}

// ---------------- persistent GRU recurrence kernel -----------------------------
__global__ void __launch_bounds__(NTHR, 1)
gru_step_kernel(const int* __restrict__ X,
                const float* __restrict__ Wr_x, const float* __restrict__ b_r,
                const float* __restrict__ Wz_x, const float* __restrict__ b_z,
                const float* __restrict__ Wh_x, const float* __restrict__ b_h,
                const float* __restrict__ Wr_h, const float* __restrict__ Wz_h,
                const float* __restrict__ Wh_h)
{
    extern __shared__ float smem[];
    float* sA   = smem;                    // [k][c] -> {wr,wr,wz,wz}   (128 KB)
    float* sB   = sA + HID * CPC * 4;      // [k][c] -> wh (non-dup)    (32 KB)
    float* ring = sB + HID * CPC;          // 2 groups x 2 slots x 2048 (32 KB)
    float* z_s  = ring + 8192;             // z gate cache [c][b]       (2 KB)
    float* red  = z_s + CPC * Bsz;         // k-split reduction buffer  (8 KB)
    int*   tok  = (int*)(red + 2048);      // tokens for this step
    float* bias = (float*)(tok + Bsz);     // b_r | b_z | b_h (8 each)

    const int tid = threadIdx.x;
    const int cb  = blockIdx.x;
    const int c0  = cb * CPC;

    // barrier stamp base: uniform across CTAs (all flags equal after any run)
    unsigned bstamp = g_flags[cb];

    // ---- preload weight slices into smem ----
    for (int idx = tid; idx < HID * CPC; idx += NTHR) {
        int k = idx / CPC, c = idx % CPC;
        float wr = Wr_h[k * HID + c0 + c];
        float wz = Wz_h[k * HID + c0 + c];
        sA[idx * 4 + 0] = wr; sA[idx * 4 + 1] = wr;
        sA[idx * 4 + 2] = wz; sA[idx * 4 + 3] = wz;
        sB[idx] = Wh_h[k * HID + c0 + c];
    }
    if (tid < CPC)          bias[tid] = b_r[c0 + tid];
    else if (tid < 2 * CPC) bias[tid] = b_z[c0 + tid - CPC];
    else if (tid < 3 * CPC) bias[tid] = b_h[c0 + tid - 2 * CPC];

    // zero this CTA's columns of h (h0 = 0); must be re-done every launch
    for (int idx = tid; idx < CPC * Bsz; idx += NTHR)
        g_hT[(c0 + idx / Bsz) * Bsz + (idx % Bsz)] = 0.0f;

    gbar(++bstamp);

    // GEMM thread mapping: k-split in 2 groups, each 16 bq x 8 c threads,
    // each thread accumulates 4 batch rows (two f32x2 pairs) for its column.
    const int kg    = tid >> 7;           // 0..1  (k half)
    const int r128  = tid & 127;
    const int bq    = r128 >> 3;          // 0..15 (batch quad)
    const int c     = r128 & 7;           // 0..7  (column within CTA)
    const int kbase = kg * (HID / 2);
    float* myring   = ring + kg * 2 * 2048;   // 2 slots of 2048 floats
    const int barid = 1 + kg;

    // postproc mapping: 32 batch-pairs x 8 cols
    const int bp    = tid >> 3;           // 0..31
    const int cpp   = tid & 7;
    const int cc_pp = c0 + cpp;

    for (int t = 0; t < Tlen; ++t) {
        if (tid < Bsz) tok[tid] = X[tid * Tlen + t];
        __syncthreads();

        // prefetch x-gathers for this step (consumed in postprocs, hidden by GEMM)
        const int tk0 = tok[bp * 2], tk1 = tok[bp * 2 + 1];
        const float xr0 = __ldg(&Wr_x[tk0 * HID + cc_pp]);
        const float xr1 = __ldg(&Wr_x[tk1 * HID + cc_pp]);
        const float xz0 = __ldg(&Wz_x[tk0 * HID + cc_pp]);
        const float xz1 = __ldg(&Wz_x[tk1 * HID + cc_pp]);
        const float xh0 = __ldg(&Wh_x[tk0 * HID + cc_pp]);
        const float xh1 = __ldg(&Wh_x[tk1 * HID + cc_pp]);

        // ======================= Phase A: r,z = h @ [Wr_h|Wz_h] ================
        unsigned long long aR0 = 0, aR1 = 0, aZ0 = 0, aZ1 = 0;
        {
            const float* gsrc = g_hT + kbase * Bsz;
            copy_chunk(myring, gsrc, r128);                      // chunk 0 -> slot 0
            #pragma unroll 1
            for (int ch = 0; ch < NCHUNK; ++ch) {
                wait_cp0();
                named_bar(barid);
                if (ch + 1 < NCHUNK)
                    copy_chunk(myring + ((ch + 1) & 1) * 2048,
                               gsrc + (ch + 1) * 2048, r128);
                const float* hs  = myring + (ch & 1) * 2048 + bq * 4;
                const float* wpb = sA + ((kbase + ch * CHUNK_K) * CPC + c) * 4;
                #pragma unroll
                for (int kl = 0; kl < CHUNK_K; ++kl) {
                    ulonglong2 hv = *(const ulonglong2*)(hs + kl * Bsz);
                    ulonglong2 w  = *(const ulonglong2*)(wpb + kl * CPC * 4);
                    ffma2(aR0, hv.x, w.x);
                    ffma2(aR1, hv.y, w.x);
                    ffma2(aZ0, hv.x, w.y);
                    ffma2(aZ1, hv.y, w.y);
                }
            }
        }
        {   // write k-split partials: red[((kg*B + b)*CPC + c)*2 + {r,z}]
            float r0, r1, r2, r3, z0, z1, z2, z3;
            unpack2(aR0, r0, r1); unpack2(aR1, r2, r3);
            unpack2(aZ0, z0, z1); unpack2(aZ1, z2, z3);
            float* rp = red + ((kg * Bsz + bq * 4) * CPC + c) * 2;
            rp[0] = r0; rp[1] = z0; rp += CPC * 2;
            rp[0] = r1; rp[1] = z1; rp += CPC * 2;
            rp[0] = r2; rp[1] = z2; rp += CPC * 2;
            rp[0] = r3; rp[1] = z3;
        }
        __syncthreads();
        {   // gates + r*h for this CTA's columns
            #pragma unroll
            for (int j = 0; j < 2; ++j) {
                int b = bp * 2 + j;
                float sR = red[(b * CPC + cpp) * 2 + 0] +
                           red[((Bsz + b) * CPC + cpp) * 2 + 0];
                float sZ = red[(b * CPC + cpp) * 2 + 1] +
                           red[((Bsz + b) * CPC + cpp) * 2 + 1];
                float xr = j ? xr1 : xr0;
                float xz = j ? xz1 : xz0;
                float rv = sigmoidf_(sR + xr + bias[cpp]);
                float zv = sigmoidf_(sZ + xz + bias[CPC + cpp]);
                float hold = g_hT[cc_pp * Bsz + b];
                z_s[cpp * Bsz + b]  = zv;
                g_rhT[cc_pp * Bsz + b] = rv * hold;
            }
        }
        gbar(++bstamp);

        // ======================= Phase B: htilde = (r*h) @ Wh_h ================
        unsigned long long aH0 = 0, aH1 = 0;
        {
            const float* gsrc = g_rhT + kbase * Bsz;
            copy_chunk(myring, gsrc, r128);                      // chunk 0 -> slot 0
            #pragma unroll 1
            for (int ch = 0; ch < NCHUNK; ++ch) {
                wait_cp0();
                named_bar(barid);
                if (ch + 1 < NCHUNK)
                    copy_chunk(myring + ((ch + 1) & 1) * 2048,
                               gsrc + (ch + 1) * 2048, r128);
                const float* hs  = myring + (ch & 1) * 2048 + bq * 4;
                const float* wpb = sB + (kbase + ch * CHUNK_K) * CPC + c;
                #pragma unroll
                for (int kl = 0; kl < CHUNK_K; ++kl) {
                    ulonglong2 hv = *(const ulonglong2*)(hs + kl * Bsz);
                    float ws = wpb[kl * CPC];
                    unsigned long long wpk;
                    asm("mov.b64 %0, {%1, %1};" : "=l"(wpk) : "f"(ws));
                    ffma2(aH0, hv.x, wpk);
                    ffma2(aH1, hv.y, wpk);
                }
            }
        }
        {
            float h0, h1, h2, h3;
            unpack2(aH0, h0, h1); unpack2(aH1, h2, h3);
            float* rp = red + (kg * Bsz + bq * 4) * CPC + c;
            rp[0] = h0; rp[CPC] = h1; rp[2 * CPC] = h2; rp[3 * CPC] = h3;
        }
        __syncthreads();
        {   // h update + history write
            #pragma unroll
            for (int j = 0; j < 2; ++j) {
                int b = bp * 2 + j;
                float sH = red[b * CPC + cpp] + red[(Bsz + b) * CPC + cpp];
                float xh = j ? xh1 : xh0;
                float ht = tanhf(sH + xh + bias[2 * CPC + cpp]);
                float zv = z_s[cpp * Bsz + b];
                float hold = g_hT[cc_pp * Bsz + b];
                float hn = zv * hold + (1.0f - zv) * ht;
                g_hT[cc_pp * Bsz + b] = hn;
                g_hist[((size_t)t * HID + cc_pp) * Bsz + b] = hn;
            }
        }
        gbar(++bstamp);
    }
}

// ---------------- output head: out[b][t][v] = hist[t][:][b] . W_o[:,v] + b_o ---
#define KC 128
__global__ void __launch_bounds__(256)
head_kernel(const float* __restrict__ W_o, const float* __restrict__ b_o,
            float* __restrict__ out)
{
    extern __shared__ float swo[];          // KC x VOC chunk of W_o (64 KB)
    const int t   = blockIdx.x;
    const int tid = threadIdx.x;
    const int b   = tid >> 2;               // 0..63
    const int v0  = (tid & 3) * 32;         // 32 vocab cols per thread

    unsigned long long acc[16];
    #pragma unroll
    for (int i = 0; i < 16; ++i) acc[i] = 0ull;

    for (int kc = 0; kc < HID; kc += KC) {
        __syncthreads();
        for (int i = tid; i < KC * VOC; i += 256)
            swo[i] = W_o[kc * VOC + i];
        __syncthreads();

        const float* hp = g_hist + ((size_t)t * HID + kc) * Bsz + b;
        #pragma unroll 1
        for (int kk = 0; kk < KC; kk += 8) {
            float hv[8];
            #pragma unroll
            for (int u = 0; u < 8; ++u) hv[u] = __ldcg(hp + (kk + u) * Bsz);
            #pragma unroll
            for (int u = 0; u < 8; ++u) {
                unsigned long long hs;
                asm("mov.b64 %0, {%1, %1};" : "=l"(hs) : "f"(hv[u]));
                const float* wrow = swo + (kk + u) * VOC + v0;
                #pragma unroll
                for (int q = 0; q < 8; ++q) {
                    ulonglong2 w = *(const ulonglong2*)(wrow + q * 4);
                    ffma2(acc[q * 2 + 0], hs, w.x);
                    ffma2(acc[q * 2 + 1], hs, w.y);
                }
            }
        }
    }

    float* op = out + ((size_t)b * Tlen + t) * VOC + v0;
    #pragma unroll
    for (int q = 0; q < 16; ++q) {
        float lo, hi;
        unpack2(acc[q], lo, hi);
        int v = v0 + q * 2;
        op[q * 2 + 0] = lo + b_o[v + 0];
        op[q * 2 + 1] = hi + b_o[v + 1];
    }
}

// ---------------- launch ------------------------------------------------------
extern "C" void kernel_launch(void* const* d_in, const int* in_sizes, int n_in,
                              void* d_out, int out_size)
{
    const int*   X    = (const int*)  d_in[0];
    const float* Wr_x = (const float*)d_in[1];
    const float* Wr_h = (const float*)d_in[2];
    const float* b_r  = (const float*)d_in[3];
    const float* Wz_x = (const float*)d_in[4];
    const float* Wz_h = (const float*)d_in[5];
    const float* b_z  = (const float*)d_in[6];
    const float* Wh_x = (const float*)d_in[7];
    const float* Wh_h = (const float*)d_in[8];
    const float* b_h  = (const float*)d_in[9];
    const float* W_o  = (const float*)d_in[10];
    const float* b_o  = (const float*)d_in[11];
    float* out = (float*)d_out;

    // smem: sA 32768f + sB 8192f + ring 8192f + z_s 512f + red 2048f
    //       + tok 64i + bias 32f
    size_t smem1 = (size_t)(HID * CPC * 4 + HID * CPC + 8192 + CPC * Bsz + 2048)
                 * sizeof(float) + Bsz * sizeof(int) + 32 * sizeof(float);
    size_t smem2 = (size_t)KC * VOC * sizeof(float);

    cudaFuncSetAttribute(gru_step_kernel,
                         cudaFuncAttributeMaxDynamicSharedMemorySize, (int)smem1);
    cudaFuncSetAttribute(head_kernel,
                         cudaFuncAttributeMaxDynamicSharedMemorySize, (int)smem2);

    gru_step_kernel<<<GRID, NTHR, smem1>>>(X, Wr_x, b_r, Wz_x, b_z, Wh_x, b_h,
                                           Wr_h, Wz_h, Wh_h);
    head_kernel<<<Tlen, 256, smem2>>>(W_o, b_o, out);
}